// round 8
// baseline (speedup 1.0000x reference)
#include <cuda_runtime.h>
#include <cstdint>

// Problem constants
#define T_DIM   16
#define M_DIM   1024
#define K_DIM   4096          // 4*M
#define N_NODES 10000
#define N_IN    8000
#define N_B     100
#define TILE_I  512           // i-tile in shared: 16t * 512i * 4B = 32KB
#define N_TILES (K_DIM / TILE_I)          // 8
#define STEPS_TOTAL 64                    // 1024 quads / 16 qsub-lanes

typedef unsigned long long u64;
typedef ulonglong2 ull2;

// Scratch (no cudaMalloc allowed)
__device__ float g_xout[T_DIM * K_DIM];          // x_out[t][i], 256KB
__device__ float g_f[N_NODES * T_DIM * 2];       // f[n][t][o] as float2 pairs
__device__ int   g_mask[N_NODES];
__device__ int   g_list[N_NODES];
__device__ int   g_count;

// ---- packed f32x2 helpers (sm_103a) ----
__device__ __forceinline__ u64 pack2(float v) {
    u64 r;
    unsigned u = __float_as_uint(v);
    asm("mov.b64 %0, {%1, %1};" : "=l"(r) : "r"(u));
    return r;
}
__device__ __forceinline__ void fma2(u64& acc, u64 a, u64 b) {
    asm("fma.rn.f32x2 %0, %1, %2, %0;" : "+l"(acc) : "l"(a), "l"(b));
}
__device__ __forceinline__ void add2(u64& a, u64 b) {
    asm("add.rn.f32x2 %0, %0, %1;" : "+l"(a) : "l"(b));
}

// ---- 1) build x_out permutation, clear mask/count ----
__global__ void k_prep(const float* __restrict__ x) {
    int idx = blockIdx.x * blockDim.x + threadIdx.x;
    if (idx < T_DIM * K_DIM) {
        int t = idx >> 12;
        int c = idx & 4095;
        int m = c >> 2;
        int j = c & 3;
        int p = (j == 0) ? 0 : (j == 3) ? 1 : 2;   // [x0, x2, x2, x1]
        g_xout[idx] = x[(t * 3 + p) * M_DIM + m];
    }
    if (idx < N_NODES) g_mask[idx] = 0;
    if (idx == 0) g_count = 0;
}

// ---- 2) mark + compact in one pass (atomicExch dedup) ----
__global__ void k_markcompact(const int* __restrict__ node_in,
                              const int* __restrict__ top, const int* __restrict__ bottom,
                              const int* __restrict__ left, const int* __restrict__ right) {
    int idx = blockIdx.x * blockDim.x + threadIdx.x;
    int v = 0;
    if      (idx < N_IN)           v = node_in[idx];
    else if (idx < N_IN + 1*N_B)   v = top[idx - N_IN];
    else if (idx < N_IN + 2*N_B)   v = bottom[idx - N_IN - 1*N_B];
    else if (idx < N_IN + 3*N_B)   v = left[idx - N_IN - 2*N_B];
    else if (idx < N_IN + 4*N_B)   v = right[idx - N_IN - 3*N_B];
    if (v > 0) {
        if (atomicExch(&g_mask[v - 1], 1) == 0) {
            int p = atomicAdd(&g_count, 1);
            g_list[p] = v - 1;
        }
    }
}

// ---- 3) main GEMM ----
// Warp = 4 nodes. Lane = (qsub 0..15, th 0..1): qsub indexes i-quads, th splits
// the 16 t-values into two halves of 8 (both halves load identical weight
// addresses -> coalescer dedups). acc = 4 nodes x 8 t = 64 regs/lane.
// Weights double-buffered in registers (streaming __ldcs); x staged in smem.

__device__ __forceinline__ void loadW(ull2 b[8],
                                      const ull2* __restrict__ w0, const ull2* __restrict__ w1,
                                      const ull2* __restrict__ w2, const ull2* __restrict__ w3,
                                      int q) {
    b[0] = __ldcs(w0 + 2*q); b[1] = __ldcs(w0 + 2*q + 1);
    b[2] = __ldcs(w1 + 2*q); b[3] = __ldcs(w1 + 2*q + 1);
    b[4] = __ldcs(w2 + 2*q); b[5] = __ldcs(w2 + 2*q + 1);
    b[6] = __ldcs(w3 + 2*q); b[7] = __ldcs(w3 + 2*q + 1);
}

__device__ __forceinline__ void stepCompute(u64 acc[4][8], const ull2 b[8],
                                            const float4* __restrict__ xs4,
                                            int th, int sidx) {
    #pragma unroll
    for (int tl = 0; tl < 8; ++tl) {
        float4 xq = xs4[(tl + 8 * th) * (TILE_I / 4) + sidx];
        u64 x0 = pack2(xq.x), x1 = pack2(xq.y), x2 = pack2(xq.z), x3 = pack2(xq.w);
        #pragma unroll
        for (int k = 0; k < 4; ++k) {
            fma2(acc[k][tl], b[2*k].x,     x0);
            fma2(acc[k][tl], b[2*k].y,     x1);
            fma2(acc[k][tl], b[2*k + 1].x, x2);
            fma2(acc[k][tl], b[2*k + 1].y, x3);
        }
    }
}

__global__ void __launch_bounds__(128, 3)
k_compute(const float* __restrict__ weight) {
    __shared__ float4 xs4[T_DIM * (TILE_I / 4)];   // 32KB

    const int count = g_count;
    const int blockBase = blockIdx.x * 16;          // 4 warps * 4 nodes
    if (blockBase >= count) return;                 // whole CTA inactive

    const int warp = threadIdx.x >> 5;
    const int lane = threadIdx.x & 31;
    const int qsub = lane & 15;
    const int th   = lane >> 4;
    const int qbase = blockBase + warp * 4;
    const bool active = (qbase < count);

    int n0 = 0, n1 = 0, n2 = 0, n3 = 0;
    if (active) {
        int q1i = qbase + 1, q2i = qbase + 2, q3i = qbase + 3;
        n0 = g_list[qbase];
        n1 = g_list[q1i < count ? q1i : count - 1];
        n2 = g_list[q2i < count ? q2i : count - 1];
        n3 = g_list[q3i < count ? q3i : count - 1];
    }
    const ull2* __restrict__ wb = (const ull2*)weight;   // row = 2048 ull2
    const ull2* __restrict__ w0 = wb + (size_t)n0 * (K_DIM / 2);
    const ull2* __restrict__ w1 = wb + (size_t)n1 * (K_DIM / 2);
    const ull2* __restrict__ w2 = wb + (size_t)n2 * (K_DIM / 2);
    const ull2* __restrict__ w3 = wb + (size_t)n3 * (K_DIM / 2);

    u64 acc[4][8];
    #pragma unroll
    for (int k = 0; k < 4; ++k)
        #pragma unroll
        for (int tl = 0; tl < 8; ++tl) acc[k][tl] = 0ULL;

    ull2 A[8], B[8];
    if (active) loadW(A, w0, w1, w2, w3, qsub);     // gstep 0

    const float4* __restrict__ gx4 = (const float4*)g_xout;   // [16][1024]

    #pragma unroll 1
    for (int tile = 0; tile < N_TILES; ++tile) {
        __syncthreads();
        // stage 32KB x tile (coalesced float4)
        #pragma unroll
        for (int j = threadIdx.x; j < T_DIM * (TILE_I / 4); j += 128) {
            int t = j >> 7;                 // /128
            int c = j & 127;
            xs4[j] = gx4[t * (K_DIM / 4) + tile * (TILE_I / 4) + c];
        }
        __syncthreads();

        #pragma unroll
        for (int sl = 0; sl < 8; sl += 2) {
            const int gstep = tile * 8 + sl;
            if (active) {
                loadW(B, w0, w1, w2, w3, qsub + 16 * (gstep + 1));
                stepCompute(acc, A, xs4, th, qsub + 16 * sl);
                const int qA = (gstep + 2 < STEPS_TOTAL) ? qsub + 16 * (gstep + 2) : qsub;
                loadW(A, w0, w1, w2, w3, qA);
                stepCompute(acc, B, xs4, th, qsub + 16 * (sl + 1));
            }
        }
    }

    if (!active) return;

    // butterfly reduce over the 16 qsub lanes (stay within t-half: d < 16)
    #pragma unroll
    for (int k = 0; k < 4; ++k)
        #pragma unroll
        for (int tl = 0; tl < 8; ++tl) {
            u64 v = acc[k][tl];
            #pragma unroll
            for (int d = 8; d > 0; d >>= 1)
                add2(v, __shfl_xor_sync(0xffffffffu, v, d));
            acc[k][tl] = v;
        }

    // every lane now holds full sums for its t-half; each lane writes 2 of the
    // 32 (node, tl) elements per half
    float2* __restrict__ f2 = (float2*)g_f;
    #pragma unroll
    for (int rep = 0; rep < 2; ++rep) {
        int e = qsub + 16 * rep;            // 0..31
        int k = e >> 3;
        int tl = e & 7;
        int nk = (k == 0) ? n0 : (k == 1) ? n1 : (k == 2) ? n2 : n3;
        u64 v = acc[k][tl];
        float lo = __uint_as_float((unsigned)(v & 0xffffffffULL));
        float hi = __uint_as_float((unsigned)(v >> 32));
        f2[nk * 16 + (tl + 8 * th)] = make_float2(lo, hi);
    }
}

// ---- 4) fused epilogue: float4 gather (blocks 0..249) + boundary sums (block 250)
__global__ void k_post(const int* __restrict__ node_in,
                       const int* __restrict__ top, const int* __restrict__ bottom,
                       const int* __restrict__ left, const int* __restrict__ right,
                       float* __restrict__ out) {
    if (blockIdx.x < 250) {
        int e = blockIdx.x * 256 + threadIdx.x;   // covers N_IN*8 = 64000 float4
        int k = e >> 3;
        int r = e & 7;
        ((float4*)out)[e] = ((const float4*)g_f)[(node_in[k] - 1) * 8 + r];
    } else {
        __shared__ float s[4][16];
        int tid = threadIdx.x;
        float* ob = out + N_IN * 32;
        if (tid < 64) {
            int r = tid >> 4;                     // 0 top, 1 bottom, 2 left, 3 right
            int t = tid & 15;
            const int* arr = (r == 0) ? top : (r == 1) ? bottom : (r == 2) ? left : right;
            int o = (r < 2) ? 1 : 0;
            float sum = 0.0f;
            for (int b = 0; b < N_B; ++b)
                sum += g_f[(arr[b] - 1) * 32 + t * 2 + o];
            s[r][t] = sum;
            ob[r * 16 + t] = sum;
        }
        __syncthreads();
        if (tid < 32) {
            int r = tid >> 4;                     // 0: top+bottom, 1: left+right
            int t = tid & 15;
            ob[(4 + r) * 16 + t] = s[2 * r][t] + s[2 * r + 1][t];
        }
    }
}

extern "C" void kernel_launch(void* const* d_in, const int* in_sizes, int n_in,
                              void* d_out, int out_size) {
    const float* x       = (const float*)d_in[0];
    const float* weight  = (const float*)d_in[1];
    const int*   node_in = (const int*)d_in[2];
    const int*   top     = (const int*)d_in[3];
    const int*   bottom  = (const int*)d_in[4];
    const int*   left    = (const int*)d_in[5];
    const int*   right   = (const int*)d_in[6];
    float* out = (float*)d_out;
    (void)in_sizes; (void)n_in; (void)out_size;

    k_prep<<<(T_DIM * K_DIM + 255) / 256, 256>>>(x);
    k_markcompact<<<(N_IN + 4 * N_B + 255) / 256, 256>>>(node_in, top, bottom, left, right);
    k_compute<<<(N_NODES + 15) / 16, 128>>>(weight);
    k_post<<<251, 256>>>(node_in, top, bottom, left, right, out);
}